// round 14
// baseline (speedup 1.0000x reference)
#include <cuda_runtime.h>
#include <cstddef>

// Problem constants
#define NUM_V  100000
#define NUM_R  1000
#define ARITY  3
#define DD     128     // D
#define DI     192     // D + I
#define HH     128     // H
#define BB     4096    // B
#define NN     64      // N

// Scratch (device globals: no allocation allowed)
__device__ float g_Vp[(size_t)NUM_V * HH];   // 51.2 MB
__device__ float g_Rp[(size_t)NUM_R * HH];   // 512 KB
__device__ float g_PE[HH];

using u64 = unsigned long long;

__device__ __forceinline__ u64 bcast2(float a) {
    u64 r;
    asm("mov.b64 %0, {%1, %1};" : "=l"(r) : "f"(a));
    return r;
}
__device__ __forceinline__ void fma2(u64 &d, u64 a, u64 b) {
    asm("fma.rn.f32x2 %0, %1, %2, %3;" : "=l"(d) : "l"(a), "l"(b), "l"(d));
}

// ---------------------------------------------------------------------------
// Kernel B (merged): Vp GEMM + Rp GEMM + PE, one launch.
//   bids [0, NB_VP)            : one 64-row Vp tile each
//   bids [NB_VP, NB_VP+500)    : two Rp rows each (256 thr = 2 x 128)
//   bid  NB_VP+500             : PE block
// The trailing rp/pe blocks are issued after all vp tiles, so they fill the
// SM slots that idle during vp's ragged last wave (1563 tiles over 296
// slots = 5.28 tiles/slot) instead of costing a separate serial launch.
//
// Vp math: Vp[v,h] = sum_k V[v,k]*WV[k,h] + bV[h], fp32 via packed f32x2.
// 256 threads, 64 rows/tile, 8 rows/thread => each 16B WV load feeds 32
// lane-MACs, keeping l1tex under the FFMA2-pipe floor. sV reads are
// warp-broadcast (lanes share rg), so LDS bandwidth is negligible.
// ---------------------------------------------------------------------------
#define VP_ROWS 64
#define VP_RPT  8   // rows per thread
#define NB_VP   ((NUM_V + VP_ROWS - 1) / VP_ROWS)   // 1563
#define NB_RP   (NUM_R / 2)                          // 500
__global__ __launch_bounds__(256, 2)
void vp_rp_pe_kernel(const float* __restrict__ V,
                     const float* __restrict__ WV,
                     const float* __restrict__ bV,
                     const float* __restrict__ R,
                     const float* __restrict__ WR,
                     const float* __restrict__ bR,
                     const float* __restrict__ P,
                     const float* __restrict__ WP,
                     const float* __restrict__ bP) {
    __shared__ float sV[VP_ROWS][DI];   // 48 KB (rp path reuses a corner)
    const int tid = threadIdx.x;
    const int bid = blockIdx.x;

    if (bid < NB_VP) {
        // ----------------- Vp tile path -----------------
        const int row0 = bid * VP_ROWS;
        {
            const int valid_f4 = (NUM_V - row0 >= VP_ROWS)
                               ? VP_ROWS * DI / 4
                               : (NUM_V - row0) * DI / 4;
            const float4* __restrict__ src =
                reinterpret_cast<const float4*>(V + (size_t)row0 * DI);
            float4* dst = reinterpret_cast<float4*>(&sV[0][0]);
#pragma unroll
            for (int i = 0; i < 12; i++) {
                int idx = tid + i * 256;
                float4 z = make_float4(0.f, 0.f, 0.f, 0.f);
                dst[idx] = (idx < valid_f4) ? __ldg(src + idx) : z;
            }
        }
        __syncthreads();

        const int hq = tid & 31;
        const int rg = tid >> 5;
        const int h0 = hq * 4;

        u64 acc[VP_RPT][2];
        {
            ulonglong2 bv = __ldg(reinterpret_cast<const ulonglong2*>(bV + h0));
#pragma unroll
            for (int r = 0; r < VP_RPT; r++) { acc[r][0] = bv.x; acc[r][1] = bv.y; }
        }

        for (int k0 = 0; k0 < DI; k0 += 4) {
            float4 v[VP_RPT];
#pragma unroll
            for (int r = 0; r < VP_RPT; r++)
                v[r] = *reinterpret_cast<const float4*>(&sV[rg * VP_RPT + r][k0]);
#pragma unroll
            for (int kk = 0; kk < 4; kk++) {
                ulonglong2 w = __ldg(reinterpret_cast<const ulonglong2*>(
                    WV + (size_t)(k0 + kk) * HH + h0));
#pragma unroll
                for (int r = 0; r < VP_RPT; r++) {
                    float vs = (kk == 0) ? v[r].x : (kk == 1) ? v[r].y
                             : (kk == 2) ? v[r].z : v[r].w;
                    u64 vb = bcast2(vs);
                    fma2(acc[r][0], vb, w.x);
                    fma2(acc[r][1], vb, w.y);
                }
            }
        }

#pragma unroll
        for (int r = 0; r < VP_RPT; r++) {
            int row = row0 + rg * VP_RPT + r;
            if (row < NUM_V) {
                float4 o;
                reinterpret_cast<u64*>(&o)[0] = acc[r][0];
                reinterpret_cast<u64*>(&o)[1] = acc[r][1];
                *reinterpret_cast<float4*>(g_Vp + (size_t)row * HH + h0) = o;
            }
        }
    } else if (bid < NB_VP + NB_RP) {
        // ----------------- Rp path: 2 rows per block -----------------
        const int sub = tid >> 7;         // 0 or 1
        const int h   = tid & (DD - 1);   // 0..127
        const int row = (bid - NB_VP) * 2 + sub;
        float* sR = &sV[sub][0];          // two disjoint 128-float rows
        sR[h] = __ldg(R + row * DD + h);
        __syncthreads();
        float acc = __ldg(bR + h);
#pragma unroll 8
        for (int k = 0; k < DD; k++)
            acc = fmaf(sR[k], __ldg(WR + k * HH + h), acc);
        g_Rp[(size_t)row * HH + h] = acc;
    } else {
        // ----------------- PE path -----------------
        if (tid < HH) {
            const int h = tid;
            float prod = 1.0f;
#pragma unroll
            for (int a = 0; a < ARITY; a++) {
                float acc = __ldg(bP + h);
#pragma unroll 8
                for (int k = 0; k < DD; k++)
                    acc = fmaf(__ldg(P + a * DD + k), __ldg(WP + k * HH + h), acc);
                prod *= acc;
            }
            g_PE[h] = prod;
        }
    }
}

// ---------------------------------------------------------------------------
// Kernel C: out[b,h] = PE[h] * sum_n Rp[r[b,n],h] * Vp[e0,h]*Vp[e1,h]*Vp[e2,h]
// 128 threads per block = 4 b-rows; warp = one b-row, lane covers 4 h (float4)
// All gathered rows are 512B, warp-coalesced; Vp (51.2 MB) + Rp live in L2.
// Indices are pre-scaled to BYTE offsets and stored interleaved so the hot
// loop fetches all 4 with one LDS.128 and does only adds for addressing.
// Unroll 4 => 16 front-batched LDG.128 per scoreboard window for L2-latency
// hiding. Gather loads use the non-coherent path (__ldg): tables were written
// by a prior launch and L1D is flushed per launch, so this is safe.
// C_BPB=4 -> 1024 blocks fills the last wave (1024 = 148*6 + 136).
// ---------------------------------------------------------------------------
#define C_BPB 4
__global__ __launch_bounds__(128, 8)
void gather_kernel(const int* __restrict__ r,
                   const int* __restrict__ e,
                   float* __restrict__ out) {
    __shared__ int4 sOff[C_BPB * NN];   // 4 KB: {rp_off, v0_off, v1_off, v2_off}
    const int tid = threadIdx.x;
    const int b0 = blockIdx.x * C_BPB;

    // Cooperative index load; pre-scale to byte offsets (row * 512B)
    for (int i = tid; i < C_BPB * NN; i += 128) {
        int g = b0 * NN + i;
        int4 o;
        o.x = __ldg(r + g)               << 9;
        o.y = __ldg(e + 0 * BB * NN + g) << 9;
        o.z = __ldg(e + 1 * BB * NN + g) << 9;
        o.w = __ldg(e + 2 * BB * NN + g) << 9;
        sOff[i] = o;
    }
    __syncthreads();

    const int bl = tid >> 5;
    const int h0 = (tid & 31) * 4;

    const char* __restrict__ rpB = reinterpret_cast<const char*>(g_Rp) + h0 * 4;
    const char* __restrict__ vpB = reinterpret_cast<const char*>(g_Vp) + h0 * 4;

    float4 acc = make_float4(0.f, 0.f, 0.f, 0.f);
#pragma unroll 4
    for (int n = 0; n < NN; n++) {
        const int4 o = sOff[bl * NN + n];
        const float4 rp = __ldg(reinterpret_cast<const float4*>(rpB + o.x));
        const float4 v0 = __ldg(reinterpret_cast<const float4*>(vpB + o.y));
        const float4 v1 = __ldg(reinterpret_cast<const float4*>(vpB + o.z));
        const float4 v2 = __ldg(reinterpret_cast<const float4*>(vpB + o.w));
        acc.x = fmaf(rp.x * v0.x, v1.x * v2.x, acc.x);
        acc.y = fmaf(rp.y * v0.y, v1.y * v2.y, acc.y);
        acc.z = fmaf(rp.z * v0.z, v1.z * v2.z, acc.z);
        acc.w = fmaf(rp.w * v0.w, v1.w * v2.w, acc.w);
    }

    const float4 pe = __ldg(reinterpret_cast<const float4*>(g_PE + h0));
    float4 o = make_float4(acc.x * pe.x, acc.y * pe.y,
                           acc.z * pe.z, acc.w * pe.w);
    *reinterpret_cast<float4*>(out + (size_t)(b0 + bl) * HH + h0) = o;
}

// ---------------------------------------------------------------------------
// Launch. Inputs (metadata order): r, e, V, R, P, WV, bV, WR, bR, WP, bP
// ---------------------------------------------------------------------------
extern "C" void kernel_launch(void* const* d_in, const int* in_sizes, int n_in,
                              void* d_out, int out_size) {
    const int*   r  = (const int*)  d_in[0];
    const int*   e  = (const int*)  d_in[1];
    const float* V  = (const float*)d_in[2];
    const float* R  = (const float*)d_in[3];
    const float* P  = (const float*)d_in[4];
    const float* WV = (const float*)d_in[5];
    const float* bV = (const float*)d_in[6];
    const float* WR = (const float*)d_in[7];
    const float* bR = (const float*)d_in[8];
    const float* WP = (const float*)d_in[9];
    const float* bP = (const float*)d_in[10];
    float* out = (float*)d_out;

    vp_rp_pe_kernel<<<NB_VP + NB_RP + 1, 256>>>(V, WV, bV, R, WR, bR, P, WP, bP);
    gather_kernel<<<BB / C_BPB, 128>>>(r, e, out);
}